// round 17
// baseline (speedup 1.0000x reference)
#include <cuda_runtime.h>
#include <cuda_fp16.h>
#include <cstdint>

// ContinousActionDecoder, filter-and-rescue, 32-rows/warp fp16 screen:
//  Each warp owns TWO m16 tiles (32 rows) so every B-fragment LDS feeds two
//  HMMAs (halved smem traffic per MMA). Raw fp16 A-frags packed on load;
//  row norm folded into the threshold compare. Barrier-free hot loop,
//  2 CTAs/SM, dynamic per-query thresholds, exact fp32 rescore.

#define KD      64
#define QMAX    128
#define BM      256
#define TPB     256
#define GRIDX   296
#define MARGIN  2.5e-3f
#define CAP     (1 << 21)
#define SROWS   32
#define PGRID   148

__device__ unsigned long long g_best[QMAX];       // static zero-init
__device__ unsigned int g_seedkey[QMAX];
__device__ int g_ccnt;
__device__ unsigned long long g_cand[CAP];

__device__ __forceinline__ unsigned int fkey(float f) {
    unsigned int u = __float_as_uint(f);
    return (u & 0x80000000u) ? ~u : (u | 0x80000000u);
}
__device__ __forceinline__ float unfkey(unsigned int k) {
    unsigned int u = (k & 0x80000000u) ? (k ^ 0x80000000u) : ~k;
    return __uint_as_float(u);
}
__device__ __forceinline__ uint32_t h2pack(float lo, float hi) {
    uint32_t r;
    asm("cvt.rn.f16x2.f32 %0, %1, %2;" : "=r"(r) : "f"(hi), "f"(lo));
    return r;
}
#define MMA_F16(d, a0,a1,a2,a3, b0,b1) \
    asm volatile("mma.sync.aligned.m16n8k16.row.col.f32.f16.f16.f32 " \
        "{%0,%1,%2,%3}, {%4,%5,%6,%7}, {%8,%9}, {%0,%1,%2,%3};" \
        : "+f"((d)[0]), "+f"((d)[1]), "+f"((d)[2]), "+f"((d)[3]) \
        : "r"(a0), "r"(a1), "r"(a2), "r"(a3), "r"(b0), "r"(b1))

#define EMIT_IF(cond, q, row, s) do {                                   \
    if (cond) {                                                         \
        atomicMax(&g_seedkey[(q)], fkey(s));                            \
        int _idx = atomicAdd(&g_ccnt, 1);                               \
        if (_idx < CAP)                                                 \
            g_cand[_idx] = ((unsigned long long)(unsigned)(q) << 32) |  \
                           (unsigned long long)(unsigned)(row);         \
    }                                                                   \
} while (0)

// ---------------- prepass: exact sample scores -> per-query seed ----------
__global__ void __launch_bounds__(256)
prepass(const float* __restrict__ actions, const float* __restrict__ pred,
        int N, int Q)
{
    __shared__ float qn[QMAX * KD];
    __shared__ float rows[SROWS * KD];
    __shared__ float rinv[SROWS];
    __shared__ float qinv[QMAX];
    __shared__ unsigned int skey[QMAX];

    const int tid = threadIdx.x;
    if (tid < QMAX) {
        float iv = 0.f;
        if (tid < Q) {
            float ss = 0.f;
            for (int k = 0; k < KD; ++k) {
                float v = pred[tid * KD + k];
                ss = fmaf(v, v, ss);
            }
            iv = (ss > 1e-30f) ? rsqrtf(ss) : 0.f;
        }
        qinv[tid] = iv;
        skey[tid] = 0u;
    }
    __syncthreads();
    for (int i = tid; i < QMAX * KD; i += 256) {
        int q = i >> 6, k = i & 63;
        qn[i] = (q < Q) ? pred[q * KD + k] * qinv[q] : 0.f;
    }
    const long long total = (long long)PGRID * SROWS;
    for (int i = tid; i < SROWS * 16; i += 256) {
        int r = i >> 4, k4 = i & 15;
        long long si = (long long)blockIdx.x * SROWS + r;
        long long gr = si * N / total;
        if (gr >= N) gr = N - 1;
        *(float4*)&rows[r * KD + k4 * 4] =
            ((const float4*)actions)[gr * (KD / 4) + k4];
    }
    __syncthreads();
    if (tid < SROWS) {
        float ss = 0.f;
        for (int k = 0; k < KD; ++k) {
            float v = rows[tid * KD + k];
            ss = fmaf(v, v, ss);
        }
        rinv[tid] = (ss > 1e-30f) ? rsqrtf(ss) : 0.f;
    }
    __syncthreads();

    const int rl = tid >> 3;
    const int qg = tid & 7;
    float4 rv[16];
#pragma unroll
    for (int k = 0; k < 16; ++k) rv[k] = *(const float4*)&rows[rl * KD + k * 4];
    const float ri = rinv[rl];
#pragma unroll
    for (int j = 0; j < 16; ++j) {
        int q = qg + j * 8;
        const float4* qp = (const float4*)&qn[q * KD];
        float dot = 0.f;
#pragma unroll
        for (int k = 0; k < 16; ++k) {
            float4 b = qp[k];
            dot = fmaf(rv[k].x, b.x, dot);
            dot = fmaf(rv[k].y, b.y, dot);
            dot = fmaf(rv[k].z, b.z, dot);
            dot = fmaf(rv[k].w, b.w, dot);
        }
        if (q < Q) atomicMax(&skey[q], fkey(dot * ri));
    }
    __syncthreads();
    if (tid < QMAX && tid < Q) atomicMax(&g_seedkey[tid], skey[tid]);
}

// ---------------- phase 1: 32-rows/warp screened MMA -----------------------
extern "C" __global__ void __launch_bounds__(TPB, 2)
sim_argmax(const float* __restrict__ actions, const float* __restrict__ pred,
           int N, int Q)
{
    __shared__ float invb[QMAX];
    __shared__ float tf_s[QMAX];
    __shared__ uint2 Bf[2048];                 // 16 KB query frags

    const int tid  = threadIdx.x;
    const int lane = tid & 31;
    const int w    = tid >> 5;
    const int rw   = lane >> 2;
    const int c4   = lane & 3;
    const int Rb   = w * 32;                   // warp owns 32 rows

    if (tid < QMAX) {
        float iv = 0.f;
        if (tid < Q) {
            float ss = 0.f;
            for (int k = 0; k < KD; ++k) {
                float v = pred[tid * KD + k];
                ss = fmaf(v, v, ss);
            }
            iv = (ss > 1e-30f) ? rsqrtf(ss) : 0.f;
        }
        invb[tid] = iv;
        tf_s[tid] = (tid < Q) ? (unfkey(g_seedkey[tid]) - MARGIN) : 3.4e38f;
    }
    __syncthreads();

    // B fragments once: [ks][nt][lane] -> uint2 {bh(k0,k1), bh(k+8)}
#pragma unroll
    for (int i = 0; i < 8; ++i) {
        int slot = tid + i * TPB;              // 0..2047
        int ks = slot >> 9;
        int nt = (slot >> 5) & 15;
        int l  = slot & 31;
        int q  = nt * 8 + (l >> 2);
        int k0 = ks * 16 + (l & 3) * 2;
        float iv = invb[q];
        float x0 = 0.f, x1 = 0.f, x2 = 0.f, x3 = 0.f;
        if (q < Q) {
            x0 = pred[q * KD + k0]     * iv;
            x1 = pred[q * KD + k0 + 1] * iv;
            x2 = pred[q * KD + k0 + 8] * iv;
            x3 = pred[q * KD + k0 + 9] * iv;
        }
        uint2 v;
        v.x = h2pack(x0, x1);
        v.y = h2pack(x2, x3);
        Bf[slot] = v;
    }
    __syncthreads();                            // last barrier before loop

    const long long ntiles = ((long long)N + BM - 1) / BM;
    long long tile = blockIdx.x;

    int it = 0;
    for (; tile < ntiles; tile += GRIDX, ++it) {
        // ---- load 4 row-groups (2 m-tiles), pack RAW fp16 frags on the fly
        const long long rbase = tile * BM + Rb + rw;
        uint32_t A[2][16];
        float nrm[4];
        bool ok[4];
        float ss[4];
#pragma unroll
        for (int g = 0; g < 4; ++g) {
            long long rg = rbase + 8 * g;
            ok[g] = (rg < N);
            if (rg >= N) rg = N - 1;
            const float2* pg = (const float2*)(actions + rg * KD) + c4;
            float s = 0.f;
#pragma unroll
            for (int m = 0; m < 8; ++m) {
                float2 v = pg[4 * m];
                int ks = m >> 1, half = m & 1;
                A[g >> 1][4 * ks + 2 * half + (g & 1)] = h2pack(v.x, v.y);
                s = fmaf(v.x, v.x, s);
                s = fmaf(v.y, v.y, s);
            }
            ss[g] = s;
        }
#pragma unroll
        for (int g = 0; g < 4; ++g) {
            float s = ss[g];
            s += __shfl_xor_sync(0xffffffffu, s, 1);
            s += __shfl_xor_sync(0xffffffffu, s, 2);
            nrm[g] = fmaxf(sqrtf(s), 1e-15f);
        }

        // ---- periodic threshold refresh (racing, monotone-safe)
        if ((it & 7) == 7) {
            for (int j = lane; j < QMAX; j += 32)
                tf_s[j] = fmaxf(tf_s[j], unfkey(g_seedkey[j]) - MARGIN);
        }

#pragma unroll
        for (int hf = 0; hf < 2; ++hf) {
#pragma unroll
            for (int nc = 0; nc < 2; ++nc) {
                float d[2][4][4];
#pragma unroll
                for (int mt = 0; mt < 2; ++mt)
#pragma unroll
                    for (int n = 0; n < 4; ++n)
#pragma unroll
                        for (int c = 0; c < 4; ++c) d[mt][n][c] = 0.f;

#pragma unroll
                for (int ks = 0; ks < 4; ++ks) {
#pragma unroll
                    for (int n = 0; n < 4; ++n) {
                        int nt = hf * 8 + nc * 4 + n;
                        uint2 b = Bf[(ks * 16 + nt) * 32 + lane];
                        MMA_F16(d[0][n], A[0][4 * ks], A[0][4 * ks + 1],
                                A[0][4 * ks + 2], A[0][4 * ks + 3], b.x, b.y);
                        MMA_F16(d[1][n], A[1][4 * ks], A[1][4 * ks + 1],
                                A[1][4 * ks + 2], A[1][4 * ks + 3], b.x, b.y);
                    }
                }

                // branch-free screening over this chunk's 32 values
                float mx = -3.4e38f;
#pragma unroll
                for (int n = 0; n < 4; ++n) {
                    int nt = hf * 8 + nc * 4 + n;
                    float t0f = tf_s[nt * 8 + 2 * c4];
                    float t1f = tf_s[nt * 8 + 2 * c4 + 1];
#pragma unroll
                    for (int mt = 0; mt < 2; ++mt) {
                        float m01 = fmaxf(fmaf(-t0f, nrm[2 * mt], d[mt][n][0]),
                                          fmaf(-t1f, nrm[2 * mt], d[mt][n][1]));
                        float m23 = fmaxf(fmaf(-t0f, nrm[2 * mt + 1], d[mt][n][2]),
                                          fmaf(-t1f, nrm[2 * mt + 1], d[mt][n][3]));
                        mx = fmaxf(mx, fmaxf(m01, m23));
                    }
                }
                if (__any_sync(0xffffffffu, mx >= 0.f)) {
#pragma unroll
                    for (int n = 0; n < 4; ++n) {
                        int nt = hf * 8 + nc * 4 + n;
                        int q0 = nt * 8 + 2 * c4;
                        float t0f = tf_s[q0], t1f = tf_s[q0 + 1];
#pragma unroll
                        for (int mt = 0; mt < 2; ++mt) {
                            long long ra = rbase + 16 * mt;
                            long long rb2 = ra + 8;
                            float na = nrm[2 * mt], nb = nrm[2 * mt + 1];
                            float ia = __fdividef(1.f, na);
                            float ib = __fdividef(1.f, nb);
                            EMIT_IF(ok[2 * mt] && d[mt][n][0] >= t0f * na,
                                    q0,     ra,  d[mt][n][0] * ia);
                            EMIT_IF(ok[2 * mt] && d[mt][n][1] >= t1f * na,
                                    q0 + 1, ra,  d[mt][n][1] * ia);
                            EMIT_IF(ok[2 * mt + 1] && d[mt][n][2] >= t0f * nb,
                                    q0,     rb2, d[mt][n][2] * ib);
                            EMIT_IF(ok[2 * mt + 1] && d[mt][n][3] >= t1f * nb,
                                    q0 + 1, rb2, d[mt][n][3] * ib);
                        }
                    }
                }
            }
        }
    }
}

// ---------------- phase 2: exact rescore ----------------------------------
extern "C" __global__ void rescore(const float* __restrict__ actions,
                                   const float* __restrict__ pred, int N)
{
    int total = g_ccnt;
    if (total > CAP) total = CAP;
    const int stride = gridDim.x * blockDim.x;
    for (int i = blockIdx.x * blockDim.x + threadIdx.x; i < total; i += stride) {
        unsigned long long c = g_cand[i];
        int q = (int)(c >> 32);
        unsigned row = (unsigned)c;
        const float4* a = (const float4*)(actions + (size_t)row * KD);
        const float4* b = (const float4*)(pred + (size_t)q * KD);
        float dot = 0.f, na = 0.f;
#pragma unroll
        for (int j = 0; j < 16; ++j) {
            float4 av = a[j], bv = b[j];
            dot = fmaf(av.x, bv.x, dot);
            dot = fmaf(av.y, bv.y, dot);
            dot = fmaf(av.z, bv.z, dot);
            dot = fmaf(av.w, bv.w, dot);
            na = fmaf(av.x, av.x, na);
            na = fmaf(av.y, av.y, na);
            na = fmaf(av.z, av.z, na);
            na = fmaf(av.w, av.w, na);
        }
        float s = dot / sqrtf(fmaxf(na, 1e-30f));
        unsigned long long pk = ((unsigned long long)fkey(s) << 32) |
                                (unsigned long long)(~row);
        atomicMax(&g_best[q], pk);
    }
}

__global__ void gather(const float* __restrict__ actions,
                       float* __restrict__ out, int Q) {
    int q = blockIdx.x;
    int t = threadIdx.x;
    unsigned int idx = ~(unsigned int)(g_best[q] & 0xFFFFFFFFull);
    out[(size_t)q * KD + t] = actions[(size_t)idx * KD + t];
    __syncthreads();
    if (t == 0) {
        g_best[q] = 0ull;
        g_seedkey[q] = 0u;
        if (q == 0) g_ccnt = 0;
    }
}

extern "C" void kernel_launch(void* const* d_in, const int* in_sizes, int n_in,
                              void* d_out, int out_size) {
    int ip = 0, ia = 1;
    if (n_in >= 2 && in_sizes[0] > in_sizes[1]) { ip = 1; ia = 0; }
    const float* pred    = (const float*)d_in[ip];
    const float* actions = (const float*)d_in[ia];
    int Q = in_sizes[ip] / KD;
    if (Q > QMAX) Q = QMAX;
    int N = in_sizes[ia] / KD;

    prepass<<<PGRID, 256>>>(actions, pred, N, Q);
    sim_argmax<<<GRIDX, TPB>>>(actions, pred, N, Q);
    rescore<<<148, 256>>>(actions, pred, N);
    gather<<<Q, KD>>>(actions, (float*)d_out, Q);
}